// round 2
// baseline (speedup 1.0000x reference)
#include <cuda_runtime.h>

// MotionPrediction: B=65536, 3 layers of cyclic 4-expert MoE, dims 256.
// out[b] = Σ_e c_e[b] * (x[b] @ W_e + bias_e)   per layer (+ReLU on 1,2)
// Folded as one GEMM with K'=1024: Xd[k'] = c_{k'/256}[b] * x[b][k'%256].

#define BSZ 65536
#define NDIM 256

// Scratch (device globals: allocation-free per harness rules)
__device__ float g_H1[BSZ * NDIM];
__device__ float g_H2[BSZ * NDIM];
__device__ float4 g_coeff[BSZ];

// ---------------------------------------------------------------------------
// Per-sample expert coefficients. Must reproduce JAX's f32 arithmetic exactly
// for the discontinuous wi = int(w) % 4 (single f32 multiply -> bit-exact).
// ---------------------------------------------------------------------------
__global__ void coeff_kernel(const float* __restrict__ phi) {
    int b = blockIdx.x * blockDim.x + threadIdx.x;
    if (b >= BSZ) return;
    const float TWO_OVER_PI = (float)(2.0 / 3.14159265358979323846);
    float w  = TWO_OVER_PI * phi[b];          // same single f32 mul as reference
    int  wi  = ((int)w) & 3;                  // w in [0,4): trunc == astype(int32)
    float w2 = w * w;
    float w3 = w2 * w;                        // (w*w)*w, matches left-assoc w*w*w
    float co[4];
    co[0] = -0.5f * w + w2 - 0.5f * w3;
    co[1] = -2.5f * w2 + 1.5f * w3;
    co[2] =  0.5f * w + 2.0f * w2 - 1.5f * w3;
    co[3] = -0.5f * w2 + 0.5f * w3;
    // expert e receives coeff[i] with i = (e - wi + 1) mod 4
    float c[4];
#pragma unroll
    for (int e = 0; e < 4; ++e) c[e] = co[(e - wi + 5) & 3];
    g_coeff[b] = make_float4(c[0], c[1], c[2], c[3]);
}

// ---------------------------------------------------------------------------
// Fused cyclic-MoE layer: 64x64 output tile per block, K'=1024 in 32 chunks.
// X is pre-scaled by c_e and pre-duplicated into (x,x) u64 pairs so the inner
// loop is pure LDS.64/LDS.128 + fma.rn.f32x2 (packed fp32, 2 MACs/instr).
// ---------------------------------------------------------------------------
template <bool RELU>
__global__ __launch_bounds__(256) void layer_kernel(
    const float* __restrict__ Xin,    // [B,256]
    const float* __restrict__ W,      // [4,256,256]  (e, in, out) row-major
    const float* __restrict__ bias,   // [4,256]
    float* __restrict__ Out)          // [B,256]
{
    __shared__ unsigned long long Xd[32][65];  // duplicated, c_e-scaled x tile
    __shared__ float Ws[32][64];
    __shared__ float cs[4][64];
    __shared__ float bs[4][64];

    const int tid = threadIdx.x;
    const int tx = tid & 15;          // 16 col-threads
    const int ty = tid >> 4;          // 16 row-threads
    const int rowbase = blockIdx.x << 6;
    const int colbase = blockIdx.y << 6;

    if (tid < 64) {
        float4 c = g_coeff[rowbase + tid];
        cs[0][tid] = c.x; cs[1][tid] = c.y; cs[2][tid] = c.z; cs[3][tid] = c.w;
    }
    {   // 4 experts x 64 cols of bias
        int e = tid >> 6, n = tid & 63;
        bs[e][n] = bias[e * NDIM + colbase + n];
    }

    unsigned long long acc[4][2];
#pragma unroll
    for (int i = 0; i < 4; ++i) { acc[i][0] = 0ull; acc[i][1] = 0ull; }

    for (int chunk = 0; chunk < 32; ++chunk) {
        const int e     = chunk >> 3;          // expert = k'/256
        const int kbase = (chunk & 7) << 5;    // k within expert
        __syncthreads();                       // (also orders cs/bs on iter 0)

        // X tile 64 rows x 32 k, scaled by c_e[row], stored transposed+duplicated
#pragma unroll
        for (int u = 0; u < 8; ++u) {
            int i = tid + (u << 8);
            int r = i >> 5, c = i & 31;
            float v = Xin[(rowbase + r) * NDIM + kbase + c] * cs[e][r];
            unsigned int vu = __float_as_uint(v);
            Xd[c][r] = ((unsigned long long)vu << 32) | (unsigned long long)vu;
        }
        // W tile 32 k x 64 cols
        const float* Wg = W + e * (NDIM * NDIM) + kbase * NDIM + colbase;
#pragma unroll
        for (int u = 0; u < 8; ++u) {
            int i = tid + (u << 8);
            int r = i >> 6, c = i & 63;
            Ws[r][c] = Wg[r * NDIM + c];
        }
        __syncthreads();

#pragma unroll
        for (int kk = 0; kk < 32; ++kk) {
            float4 wv = *(const float4*)&Ws[kk][tx << 2];
            unsigned long long w01, w23;
            asm("mov.b64 %0, {%1, %2};" : "=l"(w01)
                : "r"(__float_as_uint(wv.x)), "r"(__float_as_uint(wv.y)));
            asm("mov.b64 %0, {%1, %2};" : "=l"(w23)
                : "r"(__float_as_uint(wv.z)), "r"(__float_as_uint(wv.w)));
#pragma unroll
            for (int i = 0; i < 4; ++i) {
                unsigned long long x2 = Xd[kk][(ty << 2) + i];
                asm("fma.rn.f32x2 %0, %1, %2, %0;" : "+l"(acc[i][0]) : "l"(x2), "l"(w01));
                asm("fma.rn.f32x2 %0, %1, %2, %0;" : "+l"(acc[i][1]) : "l"(x2), "l"(w23));
            }
        }
    }

    // Epilogue: + Σ_e c_e[row] * bias_e[col], optional ReLU, vectorized store
    const int r0 = ty << 2;
    const int c0 = tx << 2;
#pragma unroll
    for (int i = 0; i < 4; ++i) {
        float ce0 = cs[0][r0 + i], ce1 = cs[1][r0 + i];
        float ce2 = cs[2][r0 + i], ce3 = cs[3][r0 + i];
        float o[4];
        o[0] = __uint_as_float((unsigned)(acc[i][0] & 0xffffffffull));
        o[1] = __uint_as_float((unsigned)(acc[i][0] >> 32));
        o[2] = __uint_as_float((unsigned)(acc[i][1] & 0xffffffffull));
        o[3] = __uint_as_float((unsigned)(acc[i][1] >> 32));
#pragma unroll
        for (int j = 0; j < 4; ++j) {
            float bb = ce0 * bs[0][c0 + j] + ce1 * bs[1][c0 + j]
                     + ce2 * bs[2][c0 + j] + ce3 * bs[3][c0 + j];
            o[j] += bb;
            if (RELU) o[j] = fmaxf(o[j], 0.0f);
        }
        *(float4*)&Out[(rowbase + r0 + i) * NDIM + colbase + c0] =
            make_float4(o[0], o[1], o[2], o[3]);
    }
}

// ---------------------------------------------------------------------------
extern "C" void kernel_launch(void* const* d_in, const int* in_sizes, int n_in,
                              void* d_out, int out_size) {
    const float* X   = (const float*)d_in[0];
    const float* phi = (const float*)d_in[1];
    const float* W1  = (const float*)d_in[2];
    const float* b1  = (const float*)d_in[3];
    const float* W2  = (const float*)d_in[4];
    const float* b2  = (const float*)d_in[5];
    const float* W3  = (const float*)d_in[6];
    const float* b3  = (const float*)d_in[7];
    float* out = (float*)d_out;

    float *H1, *H2;
    cudaGetSymbolAddress((void**)&H1, g_H1);
    cudaGetSymbolAddress((void**)&H2, g_H2);

    coeff_kernel<<<BSZ / 256, 256>>>(phi);
    dim3 grid(BSZ / 64, 4);
    layer_kernel<true ><<<grid, 256>>>(X,  W1, b1, H1);
    layer_kernel<true ><<<grid, 256>>>(H1, W2, b2, H2);
    layer_kernel<false><<<grid, 256>>>(H2, W3, b3, out);
}

// round 4
// speedup vs baseline: 2.8299x; 2.8299x over previous
#include <cuda_runtime.h>
#include <cuda_bf16.h>
#include <cstdint>

// MotionPrediction: B=65536, 3 cyclic-MoE layers, dims 256, 4 experts.
// out = sum_e c_e (.) (X @ W_e + b_e), ReLU on layers 1,2.
// HMMA (mma.sync m16n8k16 bf16) with hi/lo split (3 products) -> ~fp32 accuracy.

#define BSZ  65536
#define NDIM 256

__device__ float  g_H1[BSZ * NDIM];
__device__ float  g_H2[BSZ * NDIM];
__device__ float4 g_coeff[BSZ];
__device__ __nv_bfloat16 g_Whi[4 * NDIM * NDIM];  // blocked [chunk=e*8+kc][n256][k32]
__device__ __nv_bfloat16 g_Wlo[4 * NDIM * NDIM];

// ---- SMEM map (bytes) ----
#define ASTR      528            // A row stride (264 bf16) - conflict-free ldmatrix
#define SA_LO_OFF 33792          // A_lo = A_hi + this
#define SB_OFF    67584          // B buffers
#define SB_BUF    40960          // per buffer (hi 20480 + lo 20480)
#define SB_LO     20480
#define BSTR      80             // B row stride (40 bf16)
#define SBIAS_OFF 149504
#define SM_TOTAL  153600

// ---------------------------------------------------------------- helpers
__device__ __forceinline__ uint32_t smem_u32(const void* p) {
    uint32_t a;
    asm("{ .reg .u64 t; cvta.to.shared.u64 t, %1; cvt.u32.u64 %0, t; }"
        : "=r"(a) : "l"(p));
    return a;
}
__device__ __forceinline__ void ldsm4(uint32_t* r, uint32_t a) {
    asm volatile("ldmatrix.sync.aligned.m8n8.x4.shared.b16 {%0,%1,%2,%3}, [%4];"
                 : "=r"(r[0]), "=r"(r[1]), "=r"(r[2]), "=r"(r[3]) : "r"(a));
}
__device__ __forceinline__ void mma16816(float* d, const uint32_t* a,
                                         uint32_t b0, uint32_t b1) {
    asm volatile(
        "mma.sync.aligned.m16n8k16.row.col.f32.bf16.bf16.f32 "
        "{%0,%1,%2,%3}, {%4,%5,%6,%7}, {%8,%9}, {%0,%1,%2,%3};"
        : "+f"(d[0]), "+f"(d[1]), "+f"(d[2]), "+f"(d[3])
        : "r"(a[0]), "r"(a[1]), "r"(a[2]), "r"(a[3]), "r"(b0), "r"(b1));
}
__device__ __forceinline__ void cpa16(uint32_t s, const void* g) {
    asm volatile("cp.async.cg.shared.global [%0], [%1], 16;" :: "r"(s), "l"(g));
}

// ---------------------------------------------------------------- coeff
__global__ void coeff_kernel(const float* __restrict__ phi) {
    int b = blockIdx.x * blockDim.x + threadIdx.x;
    if (b >= BSZ) return;
    const float TWO_OVER_PI = (float)(2.0 / 3.14159265358979323846);
    float w  = TWO_OVER_PI * phi[b];
    int  wi  = ((int)w) & 3;
    float w2 = w * w, w3 = w2 * w;
    float co[4];
    co[0] = -0.5f * w + w2 - 0.5f * w3;
    co[1] = -2.5f * w2 + 1.5f * w3;
    co[2] =  0.5f * w + 2.0f * w2 - 1.5f * w3;
    co[3] = -0.5f * w2 + 0.5f * w3;
    float c[4];
#pragma unroll
    for (int e = 0; e < 4; ++e) c[e] = co[(e - wi + 5) & 3];
    g_coeff[b] = make_float4(c[0], c[1], c[2], c[3]);
}

// ---------------------------------------------------------------- W convert
// W [4][256 k][256 n] f32  ->  blocked [chunk=e*8+kc][n 256][k 32] bf16 hi/lo
__global__ void convW_kernel(const float* __restrict__ W) {
    int i = blockIdx.x * 256 + threadIdx.x;      // 262144 total
    int chunk = i >> 13;
    int n = (i >> 5) & 255;
    int k = i & 31;
    int e = chunk >> 3, kc = chunk & 7;
    float w = W[((e << 8) + kc * 32 + k) * NDIM + n];
    __nv_bfloat16 h = __float2bfloat16_rn(w);
    float r = w - __bfloat162float(h);
    g_Whi[i] = h;
    g_Wlo[i] = __float2bfloat16_rn(r);
}

// ---------------------------------------------------------------- B chunk load
__device__ __forceinline__ void load_chunk(uint32_t sb, int chunk, int buf, int tid) {
    const int nq = tid >> 2, kq = tid & 3;
    const size_t gb = (size_t)chunk * 8192 + (size_t)kq * 8;
    const uint32_t s = sb + SB_OFF + buf * SB_BUF + nq * BSTR + kq * 16;
#pragma unroll
    for (int p = 0; p < 4; ++p) {
        int n = p * 64 + nq;
        cpa16(s + p * 64 * BSTR,         g_Whi + gb + (size_t)n * 32);
        cpa16(s + p * 64 * BSTR + SB_LO, g_Wlo + gb + (size_t)n * 32);
    }
}

// ---------------------------------------------------------------- layer
template <bool RELU>
__global__ void __launch_bounds__(256, 1) layer_hmma(
    const float* __restrict__ Xin,    // [B,256]
    const float* __restrict__ bias,   // [4,256]
    float* __restrict__ Out)          // [B,256]
{
    extern __shared__ char smem[];
    const uint32_t sb = smem_u32(smem);
    const int tid  = threadIdx.x;
    const int lane = tid & 31, wid = tid >> 5;
    const int mwarp = wid & 3, nwarp = wid >> 2;
    const int rowbase = blockIdx.x << 6;

    // prefetch B chunk 0 early
    load_chunk(sb, 0, 0, tid);
    asm volatile("cp.async.commit_group;" ::: "memory");

    // bias -> smem
    for (int i = tid; i < 1024; i += 256)
        ((float*)(smem + SBIAS_OFF))[i] = bias[i];

    // per-thread row coefficients
    const int gr0 = rowbase + mwarp * 16 + (lane >> 2);
    const float4 cva = g_coeff[gr0];
    const float4 cvb = g_coeff[gr0 + 8];

    // ---- A prep: X rows [rowbase, rowbase+64) -> bf16 hi/lo in smem
    {
        const int r = tid >> 2, q = tid & 3;
        const float* xp = Xin + (size_t)(rowbase + r) * NDIM + q * 64;
        char* arow = smem + r * ASTR + q * 128;
#pragma unroll
        for (int j = 0; j < 64; j += 8) {
            float4 f0 = *(const float4*)(xp + j);
            float4 f1 = *(const float4*)(xp + j + 4);
            float f[8] = {f0.x, f0.y, f0.z, f0.w, f1.x, f1.y, f1.z, f1.w};
            uint32_t h[4], l[4];
#pragma unroll
            for (int p = 0; p < 4; ++p) {
                __nv_bfloat16 h0 = __float2bfloat16_rn(f[2 * p]);
                __nv_bfloat16 h1 = __float2bfloat16_rn(f[2 * p + 1]);
                float r0 = f[2 * p]     - __bfloat162float(h0);
                float r1 = f[2 * p + 1] - __bfloat162float(h1);
                h[p] = (uint32_t)__bfloat16_as_ushort(h0)
                     | ((uint32_t)__bfloat16_as_ushort(h1) << 16);
                l[p] = (uint32_t)__bfloat16_as_ushort(__float2bfloat16_rn(r0))
                     | ((uint32_t)__bfloat16_as_ushort(__float2bfloat16_rn(r1)) << 16);
            }
            *(uint4*)(arow + 2 * j)             = make_uint4(h[0], h[1], h[2], h[3]);
            *(uint4*)(arow + SA_LO_OFF + 2 * j) = make_uint4(l[0], l[1], l[2], l[3]);
        }
    }

    // ldmatrix per-lane patterns
    const int lrow = (lane & 7) + (((lane >> 3) & 1) << 3);
    const int lkof = (lane >> 4) << 3;
    const uint32_t aBase = sb + (mwarp * 16 + lrow) * ASTR + lkof * 2;
    const uint32_t bBase = sb + SB_OFF + (nwarp * 128 + lrow) * BSTR + lkof * 2;

    float acc[64], outv[64];
#pragma unroll
    for (int i = 0; i < 64; ++i) { acc[i] = 0.f; outv[i] = 0.f; }

#pragma unroll
    for (int e = 0; e < 4; ++e) {
#pragma unroll 2
        for (int kc = 0; kc < 8; ++kc) {
            const int t = e * 8 + kc;
            const int buf = t & 1;
            if (t < 31) {
                load_chunk(sb, t + 1, buf ^ 1, tid);
                asm volatile("cp.async.commit_group;" ::: "memory");
                asm volatile("cp.async.wait_group 1;" ::: "memory");
            } else {
                asm volatile("cp.async.wait_group 0;" ::: "memory");
            }
            __syncthreads();
#pragma unroll
            for (int ks = 0; ks < 2; ++ks) {
                const int kg = kc * 32 + ks * 16;
                uint32_t ah[4], al[4];
                ldsm4(ah, aBase + kg * 2);
                ldsm4(al, aBase + SA_LO_OFF + kg * 2);
#pragma unroll
                for (int g = 0; g < 8; ++g) {
                    uint32_t bh[4], bl[4];
                    const uint32_t ba = bBase + buf * SB_BUF + g * (16 * BSTR) + ks * 32;
                    ldsm4(bh, ba);
                    ldsm4(bl, ba + SB_LO);
                    float* A0 = acc + g * 8;
                    mma16816(A0,     ah, bh[0], bh[2]);   // hi*hi tile0
                    mma16816(A0 + 4, ah, bh[1], bh[3]);   // hi*hi tile1
                    mma16816(A0,     al, bh[0], bh[2]);   // lo*hi
                    mma16816(A0 + 4, al, bh[1], bh[3]);
                    mma16816(A0,     ah, bl[0], bl[2]);   // hi*lo
                    mma16816(A0 + 4, ah, bl[1], bl[3]);
                }
            }
            __syncthreads();
        }
        // fold expert e with per-row coefficient (fp32 exact)
        const float ce0 = (e == 0) ? cva.x : (e == 1) ? cva.y : (e == 2) ? cva.z : cva.w;
        const float ce1 = (e == 0) ? cvb.x : (e == 1) ? cvb.y : (e == 2) ? cvb.z : cvb.w;
#pragma unroll
        for (int i = 0; i < 64; i += 4) {
            outv[i]     += ce0 * acc[i];     acc[i]     = 0.f;
            outv[i + 1] += ce0 * acc[i + 1]; acc[i + 1] = 0.f;
            outv[i + 2] += ce1 * acc[i + 2]; acc[i + 2] = 0.f;
            outv[i + 3] += ce1 * acc[i + 3]; acc[i + 3] = 0.f;
        }
    }

    // ---- epilogue: + sum_e c_e * b_e[n], ReLU, store
    const float* bsm = (const float*)(smem + SBIAS_OFF);
#pragma unroll
    for (int g = 0; g < 8; ++g) {
#pragma unroll
        for (int tl = 0; tl < 2; ++tl) {
            const int n0 = nwarp * 128 + g * 16 + tl * 8 + (lane & 3) * 2;
            float b00 = cva.x * bsm[n0]     + cva.y * bsm[256 + n0]
                      + cva.z * bsm[512 + n0] + cva.w * bsm[768 + n0];
            float b01 = cva.x * bsm[n0 + 1] + cva.y * bsm[256 + n0 + 1]
                      + cva.z * bsm[512 + n0 + 1] + cva.w * bsm[768 + n0 + 1];
            float b10 = cvb.x * bsm[n0]     + cvb.y * bsm[256 + n0]
                      + cvb.z * bsm[512 + n0] + cvb.w * bsm[768 + n0];
            float b11 = cvb.x * bsm[n0 + 1] + cvb.y * bsm[256 + n0 + 1]
                      + cvb.z * bsm[512 + n0 + 1] + cvb.w * bsm[768 + n0 + 1];
            const float* o = outv + g * 8 + tl * 4;
            float v0 = o[0] + b00, v1 = o[1] + b01;
            float v2 = o[2] + b10, v3 = o[3] + b11;
            if (RELU) {
                v0 = fmaxf(v0, 0.f); v1 = fmaxf(v1, 0.f);
                v2 = fmaxf(v2, 0.f); v3 = fmaxf(v3, 0.f);
            }
            float2 lo = make_float2(v0, v1), hi = make_float2(v2, v3);
            *(float2*)(Out + (size_t)gr0 * NDIM + n0)       = lo;
            *(float2*)(Out + (size_t)(gr0 + 8) * NDIM + n0) = hi;
        }
    }
}

// ---------------------------------------------------------------- launch
extern "C" void kernel_launch(void* const* d_in, const int* in_sizes, int n_in,
                              void* d_out, int out_size) {
    const float* X   = (const float*)d_in[0];
    const float* phi = (const float*)d_in[1];
    const float* W1  = (const float*)d_in[2];
    const float* b1  = (const float*)d_in[3];
    const float* W2  = (const float*)d_in[4];
    const float* b2  = (const float*)d_in[5];
    const float* W3  = (const float*)d_in[6];
    const float* b3  = (const float*)d_in[7];
    float* out = (float*)d_out;

    float *H1, *H2;
    cudaGetSymbolAddress((void**)&H1, g_H1);
    cudaGetSymbolAddress((void**)&H2, g_H2);

    cudaFuncSetAttribute(layer_hmma<true>,
                         cudaFuncAttributeMaxDynamicSharedMemorySize, SM_TOTAL);
    cudaFuncSetAttribute(layer_hmma<false>,
                         cudaFuncAttributeMaxDynamicSharedMemorySize, SM_TOTAL);

    coeff_kernel<<<BSZ / 256, 256>>>(phi);

    convW_kernel<<<1024, 256>>>(W1);
    layer_hmma<true ><<<BSZ / 64, 256, SM_TOTAL>>>(X, b1, H1);

    convW_kernel<<<1024, 256>>>(W2);
    layer_hmma<true ><<<BSZ / 64, 256, SM_TOTAL>>>(H1, b2, H2);

    convW_kernel<<<1024, 256>>>(W3);
    layer_hmma<false><<<BSZ / 64, 256, SM_TOTAL>>>(H2, b3, out);
}

// round 5
// speedup vs baseline: 3.2210x; 1.1382x over previous
#include <cuda_runtime.h>
#include <cuda_bf16.h>
#include <cstdint>

// MotionPrediction: B=65536, 3 cyclic-MoE layers, dims 256, 4 experts.
// out = sum_e c_e (.) (X @ W_e + b_e), ReLU on layers 1,2.
// HMMA mma.sync m16n8k16 bf16, hi/lo split (3 products) ~ fp32 accuracy.
// Activations carried between layers as bf16 hi/lo pairs in global.

#define BSZ  65536
#define NDIM 256

__device__ __align__(16) __nv_bfloat16 g_Whi[3 * 4 * NDIM * NDIM]; // [slot][chunk][n256][k32]
__device__ __align__(16) __nv_bfloat16 g_Wlo[3 * 4 * NDIM * NDIM];
__device__ __align__(16) __nv_bfloat16 g_Ahi[BSZ * NDIM];
__device__ __align__(16) __nv_bfloat16 g_Alo[BSZ * NDIM];
__device__ __align__(16) __nv_bfloat16 g_Bhi[BSZ * NDIM];
__device__ __align__(16) __nv_bfloat16 g_Blo[BSZ * NDIM];
__device__ float4 g_coeff[BSZ];

// ---- SMEM map (bytes) ----
#define ASTR     528                    // A row stride (256 bf16 + pad)
#define SA_LO    67584                  // A_lo = A_hi + 128*528
#define SB_OFF   135168                 // 3 B stages
#define SB_STAGE 20480                  // per stage: hi 10240 + lo 10240
#define SB_LO    10240
#define BSTR     80                     // B row stride (32 bf16 + pad)
#define SBIAS    196608                 // 512 floats
#define SM_TOTAL 198656

// ---------------------------------------------------------------- helpers
__device__ __forceinline__ uint32_t smem_u32(const void* p) {
    uint32_t a;
    asm("{ .reg .u64 t; cvta.to.shared.u64 t, %1; cvt.u32.u64 %0, t; }"
        : "=r"(a) : "l"(p));
    return a;
}
__device__ __forceinline__ void ldsm4(uint32_t* r, uint32_t a) {
    asm volatile("ldmatrix.sync.aligned.m8n8.x4.shared.b16 {%0,%1,%2,%3}, [%4];"
                 : "=r"(r[0]), "=r"(r[1]), "=r"(r[2]), "=r"(r[3]) : "r"(a));
}
__device__ __forceinline__ void mma16816(float* d, const uint32_t* a,
                                         uint32_t b0, uint32_t b1) {
    asm volatile(
        "mma.sync.aligned.m16n8k16.row.col.f32.bf16.bf16.f32 "
        "{%0,%1,%2,%3}, {%4,%5,%6,%7}, {%8,%9}, {%0,%1,%2,%3};"
        : "+f"(d[0]), "+f"(d[1]), "+f"(d[2]), "+f"(d[3])
        : "r"(a[0]), "r"(a[1]), "r"(a[2]), "r"(a[3]), "r"(b0), "r"(b1));
}
__device__ __forceinline__ void cpa16(uint32_t s, const void* g) {
    asm volatile("cp.async.cg.shared.global [%0], [%1], 16;" :: "r"(s), "l"(g));
}
__device__ __forceinline__ void split_bf16(float v, unsigned short& h, unsigned short& l) {
    __nv_bfloat16 hb = __float2bfloat16_rn(v);
    float r = v - __bfloat162float(hb);
    h = __bfloat16_as_ushort(hb);
    l = __bfloat16_as_ushort(__float2bfloat16_rn(r));
}

// ---------------------------------------------------------------- coeff
__global__ void coeff_kernel(const float* __restrict__ phi) {
    int b = blockIdx.x * blockDim.x + threadIdx.x;
    if (b >= BSZ) return;
    const float TWO_OVER_PI = (float)(2.0 / 3.14159265358979323846);
    float w  = TWO_OVER_PI * phi[b];
    int  wi  = ((int)w) & 3;
    float w2 = w * w, w3 = w2 * w;
    float co[4];
    co[0] = -0.5f * w + w2 - 0.5f * w3;
    co[1] = -2.5f * w2 + 1.5f * w3;
    co[2] =  0.5f * w + 2.0f * w2 - 1.5f * w3;
    co[3] = -0.5f * w2 + 0.5f * w3;
    float c[4];
#pragma unroll
    for (int e = 0; e < 4; ++e) c[e] = co[(e - wi + 5) & 3];
    g_coeff[b] = make_float4(c[0], c[1], c[2], c[3]);
}

// ---------------------------------------------------------------- X convert
__global__ void convX_kernel(const float* __restrict__ X) {
    size_t i = ((size_t)blockIdx.x * 256 + threadIdx.x) * 4;
    float4 f = *(const float4*)(X + i);
    float v[4] = {f.x, f.y, f.z, f.w};
    unsigned short h[4], l[4];
#pragma unroll
    for (int p = 0; p < 4; ++p) split_bf16(v[p], h[p], l[p]);
    *(uint2*)(g_Ahi + i) = make_uint2((uint32_t)h[0] | ((uint32_t)h[1] << 16),
                                      (uint32_t)h[2] | ((uint32_t)h[3] << 16));
    *(uint2*)(g_Alo + i) = make_uint2((uint32_t)l[0] | ((uint32_t)l[1] << 16),
                                      (uint32_t)l[2] | ((uint32_t)l[3] << 16));
}

// ---------------------------------------------------------------- W convert
// W [4][256 k][256 n] f32 -> blocked [chunk=e*8+kc][n 256][k 32] bf16 hi/lo
__global__ void convW_kernel(const float* __restrict__ W, int slot) {
    int i = blockIdx.x * 256 + threadIdx.x;     // 262144 per layer
    int chunk = i >> 13;
    int n = (i >> 5) & 255;
    int k = i & 31;
    int e = chunk >> 3, kc = chunk & 7;
    float w = W[((e << 8) + kc * 32 + k) * NDIM + n];
    unsigned short h, l;
    split_bf16(w, h, l);
    g_Whi[(size_t)slot * 262144 + i] = __ushort_as_bfloat16(h);
    g_Wlo[(size_t)slot * 262144 + i] = __ushort_as_bfloat16(l);
}

// ---------------------------------------------------------------- B chunk load
__device__ __forceinline__ void load_chunkB(uint32_t sb,
                                            const __nv_bfloat16* __restrict__ Whi,
                                            const __nv_bfloat16* __restrict__ Wlo,
                                            int chunk, int stage, int colbase, int tid) {
    const uint32_t dst = sb + SB_OFF + stage * SB_STAGE;
    const __nv_bfloat16* sH = Whi + (size_t)chunk * 8192;
    const __nv_bfloat16* sL = Wlo + (size_t)chunk * 8192;
#pragma unroll
    for (int u = tid; u < 512; u += 256) {     // 128 n rows x 4 x 16B
        int n = u >> 2, q = u & 3;
        cpa16(dst + n * BSTR + q * 16,         sH + (size_t)(colbase + n) * 32 + q * 8);
        cpa16(dst + SB_LO + n * BSTR + q * 16, sL + (size_t)(colbase + n) * 32 + q * 8);
    }
}

// ---------------------------------------------------------------- layer
template <bool RELU, bool BF16OUT>
__global__ void __launch_bounds__(256, 1) layer_hmma(
    const __nv_bfloat16* __restrict__ Xhi,
    const __nv_bfloat16* __restrict__ Xlo,
    const __nv_bfloat16* __restrict__ Whi,
    const __nv_bfloat16* __restrict__ Wlo,
    const float* __restrict__ bias,
    __nv_bfloat16* __restrict__ Ohi,
    __nv_bfloat16* __restrict__ Olo,
    float* __restrict__ Out)
{
    extern __shared__ char smem[];
    const uint32_t sb = smem_u32(smem);
    const int tid = threadIdx.x, lane = tid & 31, wid = tid >> 5;
    const int mtile = blockIdx.x >> 1, ch = blockIdx.x & 1;
    const int rowbase = mtile << 7, colbase = ch << 7;

    // A tile: 128 rows x 256 bf16 hi/lo via cp.async (group 0)
#pragma unroll
    for (int u = tid; u < 4096; u += 256) {
        int r = u >> 5, s = u & 31;
        cpa16(sb + r * ASTR + s * 16,         Xhi + (size_t)(rowbase + r) * NDIM + s * 8);
        cpa16(sb + SA_LO + r * ASTR + s * 16, Xlo + (size_t)(rowbase + r) * NDIM + s * 8);
    }
    asm volatile("cp.async.commit_group;" ::: "memory");
    load_chunkB(sb, Whi, Wlo, 0, 0, colbase, tid);
    asm volatile("cp.async.commit_group;" ::: "memory");
    load_chunkB(sb, Whi, Wlo, 1, 1, colbase, tid);
    asm volatile("cp.async.commit_group;" ::: "memory");

    // bias -> smem: [e][128] for this col half
    for (int i = tid; i < 512; i += 256)
        ((float*)(smem + SBIAS))[i] = bias[(i >> 7) * NDIM + colbase + (i & 127)];

    const int gr0 = rowbase + wid * 16 + (lane >> 2);
    const float4 cva = g_coeff[gr0];
    const float4 cvb = g_coeff[gr0 + 8];

    const int lrow = (lane & 7) + (((lane >> 3) & 1) << 3);
    const int lkof = (lane >> 4) << 3;
    const uint32_t aBase = sb + (wid * 16 + lrow) * ASTR + lkof * 2;
    const uint32_t bRow  = lrow * BSTR + lkof * 2;

    float acc[64], outv[64];
#pragma unroll
    for (int i = 0; i < 64; ++i) { acc[i] = 0.f; outv[i] = 0.f; }

    int t = 0;
#pragma unroll
    for (int e = 0; e < 4; ++e) {
#pragma unroll 2
        for (int kc = 0; kc < 8; ++kc) {
            if (t < 31) asm volatile("cp.async.wait_group 1;" ::: "memory");
            else        asm volatile("cp.async.wait_group 0;" ::: "memory");
            __syncthreads();
            if (t < 30) {
                load_chunkB(sb, Whi, Wlo, t + 2, (t + 2) % 3, colbase, tid);
                asm volatile("cp.async.commit_group;" ::: "memory");
            }
            const uint32_t bS = sb + SB_OFF + (t % 3) * SB_STAGE;
#pragma unroll
            for (int ks = 0; ks < 2; ++ks) {
                uint32_t ah[4], al[4];
                const uint32_t ak = aBase + (kc * 32 + ks * 16) * 2;
                ldsm4(ah, ak);
                ldsm4(al, ak + SA_LO);
#pragma unroll
                for (int gp = 0; gp < 4; ++gp) {
                    uint32_t bh0[4], bh1[4], bl0[4], bl1[4];
                    const uint32_t ba = bS + bRow + gp * (32 * BSTR) + ks * 32;
                    ldsm4(bh0, ba);
                    ldsm4(bh1, ba + 16 * BSTR);
                    ldsm4(bl0, ba + SB_LO);
                    ldsm4(bl1, ba + SB_LO + 16 * BSTR);
                    float* A0 = acc + gp * 16;
                    float* A1 = A0 + 8;
                    mma16816(A0,     ah, bh0[0], bh0[2]);
                    mma16816(A1,     ah, bh1[0], bh1[2]);
                    mma16816(A0 + 4, ah, bh0[1], bh0[3]);
                    mma16816(A1 + 4, ah, bh1[1], bh1[3]);
                    mma16816(A0,     al, bh0[0], bh0[2]);
                    mma16816(A1,     al, bh1[0], bh1[2]);
                    mma16816(A0 + 4, al, bh0[1], bh0[3]);
                    mma16816(A1 + 4, al, bh1[1], bh1[3]);
                    mma16816(A0,     ah, bl0[0], bl0[2]);
                    mma16816(A1,     ah, bl1[0], bl1[2]);
                    mma16816(A0 + 4, ah, bl0[1], bl0[3]);
                    mma16816(A1 + 4, ah, bl1[1], bl1[3]);
                }
            }
            ++t;
        }
        const float ce0 = (e == 0) ? cva.x : (e == 1) ? cva.y : (e == 2) ? cva.z : cva.w;
        const float ce1 = (e == 0) ? cvb.x : (e == 1) ? cvb.y : (e == 2) ? cvb.z : cvb.w;
#pragma unroll
        for (int i = 0; i < 64; i += 4) {
            outv[i]     += ce0 * acc[i];     acc[i]     = 0.f;
            outv[i + 1] += ce0 * acc[i + 1]; acc[i + 1] = 0.f;
            outv[i + 2] += ce1 * acc[i + 2]; acc[i + 2] = 0.f;
            outv[i + 3] += ce1 * acc[i + 3]; acc[i + 3] = 0.f;
        }
    }

    // ---- epilogue: + sum_e c_e * b_e[n], ReLU, store (f32 or bf16 hi/lo)
    const float* bsm = (const float*)(smem + SBIAS);
#pragma unroll
    for (int g = 0; g < 8; ++g) {
#pragma unroll
        for (int tl = 0; tl < 2; ++tl) {
            const int nc = g * 16 + tl * 8 + (lane & 3) * 2;  // col within half
            const int n0 = colbase + nc;
            float b00 = cva.x * bsm[nc] + cva.y * bsm[128 + nc]
                      + cva.z * bsm[256 + nc] + cva.w * bsm[384 + nc];
            float b01 = cva.x * bsm[nc + 1] + cva.y * bsm[128 + nc + 1]
                      + cva.z * bsm[256 + nc + 1] + cva.w * bsm[384 + nc + 1];
            float b10 = cvb.x * bsm[nc] + cvb.y * bsm[128 + nc]
                      + cvb.z * bsm[256 + nc] + cvb.w * bsm[384 + nc];
            float b11 = cvb.x * bsm[nc + 1] + cvb.y * bsm[128 + nc + 1]
                      + cvb.z * bsm[256 + nc + 1] + cvb.w * bsm[384 + nc + 1];
            const float* o = outv + g * 8 + tl * 4;
            float v0 = o[0] + b00, v1 = o[1] + b01;
            float v2 = o[2] + b10, v3 = o[3] + b11;
            if (RELU) {
                v0 = fmaxf(v0, 0.f); v1 = fmaxf(v1, 0.f);
                v2 = fmaxf(v2, 0.f); v3 = fmaxf(v3, 0.f);
            }
            if (BF16OUT) {
                unsigned short h0, l0, h1, l1, h2, l2, h3, l3;
                split_bf16(v0, h0, l0); split_bf16(v1, h1, l1);
                split_bf16(v2, h2, l2); split_bf16(v3, h3, l3);
                size_t p0 = (size_t)gr0 * NDIM + n0;
                size_t p1 = (size_t)(gr0 + 8) * NDIM + n0;
                *(uint32_t*)(Ohi + p0) = (uint32_t)h0 | ((uint32_t)h1 << 16);
                *(uint32_t*)(Olo + p0) = (uint32_t)l0 | ((uint32_t)l1 << 16);
                *(uint32_t*)(Ohi + p1) = (uint32_t)h2 | ((uint32_t)h3 << 16);
                *(uint32_t*)(Olo + p1) = (uint32_t)l2 | ((uint32_t)l3 << 16);
            } else {
                *(float2*)(Out + (size_t)gr0 * NDIM + n0)       = make_float2(v0, v1);
                *(float2*)(Out + (size_t)(gr0 + 8) * NDIM + n0) = make_float2(v2, v3);
            }
        }
    }
}

// ---------------------------------------------------------------- launch
extern "C" void kernel_launch(void* const* d_in, const int* in_sizes, int n_in,
                              void* d_out, int out_size) {
    const float* X   = (const float*)d_in[0];
    const float* phi = (const float*)d_in[1];
    const float* W1  = (const float*)d_in[2];
    const float* b1  = (const float*)d_in[3];
    const float* W2  = (const float*)d_in[4];
    const float* b2  = (const float*)d_in[5];
    const float* W3  = (const float*)d_in[6];
    const float* b3  = (const float*)d_in[7];
    float* out = (float*)d_out;

    __nv_bfloat16 *Whi, *Wlo, *Ahi, *Alo, *Bhi, *Blo;
    cudaGetSymbolAddress((void**)&Whi, g_Whi);
    cudaGetSymbolAddress((void**)&Wlo, g_Wlo);
    cudaGetSymbolAddress((void**)&Ahi, g_Ahi);
    cudaGetSymbolAddress((void**)&Alo, g_Alo);
    cudaGetSymbolAddress((void**)&Bhi, g_Bhi);
    cudaGetSymbolAddress((void**)&Blo, g_Blo);

    cudaFuncSetAttribute(layer_hmma<true, true>,
                         cudaFuncAttributeMaxDynamicSharedMemorySize, SM_TOTAL);
    cudaFuncSetAttribute(layer_hmma<false, false>,
                         cudaFuncAttributeMaxDynamicSharedMemorySize, SM_TOTAL);

    coeff_kernel<<<BSZ / 256, 256>>>(phi);
    convX_kernel<<<BSZ * NDIM / 1024, 256>>>(X);
    convW_kernel<<<1024, 256>>>(W1, 0);
    convW_kernel<<<1024, 256>>>(W2, 1);
    convW_kernel<<<1024, 256>>>(W3, 2);

    // L1: A -> B
    layer_hmma<true, true><<<1024, 256, SM_TOTAL>>>(
        Ahi, Alo, Whi, Wlo, b1, Bhi, Blo, nullptr);
    // L2: B -> A
    layer_hmma<true, true><<<1024, 256, SM_TOTAL>>>(
        Bhi, Blo, Whi + 262144, Wlo + 262144, b2, Ahi, Alo, nullptr);
    // L3: A -> out (f32)
    layer_hmma<false, false><<<1024, 256, SM_TOTAL>>>(
        Ahi, Alo, Whi + 524288, Wlo + 524288, b3, nullptr, nullptr, out);
}

// round 7
// speedup vs baseline: 3.3450x; 1.0385x over previous
#include <cuda_runtime.h>
#include <cuda_bf16.h>
#include <cstdint>

// MotionPrediction: B=65536, 3 cyclic-MoE layers, dims 256, 4 experts.
// out = sum_e c_e (.) (X @ W_e + b_e), ReLU on layers 1,2.
// HMMA mma.sync m16n8k16 bf16, hi/lo split (3 products) ~ fp32 accuracy.
// 512 threads/CTA (16 warps = 4/SMSP) for MMA latency hiding.

#define BSZ  65536
#define NDIM 256

__device__ __align__(16) __nv_bfloat16 g_Whi[3 * 4 * NDIM * NDIM]; // [slot][chunk][n256][k32]
__device__ __align__(16) __nv_bfloat16 g_Wlo[3 * 4 * NDIM * NDIM];
__device__ __align__(16) __nv_bfloat16 g_Ahi[BSZ * NDIM];
__device__ __align__(16) __nv_bfloat16 g_Alo[BSZ * NDIM];
__device__ __align__(16) __nv_bfloat16 g_Bhi[BSZ * NDIM];
__device__ __align__(16) __nv_bfloat16 g_Blo[BSZ * NDIM];
__device__ float4 g_coeff[BSZ];

// ---- SMEM map (bytes) ----
#define ASTR     528                    // A row stride (256 bf16 + pad)
#define SA_LO    67584                  // A_lo = A_hi + 128*528
#define SB_OFF   135168                 // 3 B stages
#define SB_STAGE 20480                  // per stage: hi 10240 + lo 10240
#define SB_LO    10240
#define BSTR     80                     // B row stride (32 bf16 + pad)
#define SBIAS    196608                 // 512 floats
#define SM_TOTAL 198656

// ---------------------------------------------------------------- helpers
__device__ __forceinline__ uint32_t smem_u32(const void* p) {
    uint32_t a;
    asm("{ .reg .u64 t; cvta.to.shared.u64 t, %1; cvt.u32.u64 %0, t; }"
        : "=r"(a) : "l"(p));
    return a;
}
__device__ __forceinline__ void ldsm4(uint32_t* r, uint32_t a) {
    asm volatile("ldmatrix.sync.aligned.m8n8.x4.shared.b16 {%0,%1,%2,%3}, [%4];"
                 : "=r"(r[0]), "=r"(r[1]), "=r"(r[2]), "=r"(r[3]) : "r"(a));
}
__device__ __forceinline__ void mma16816(float* d, const uint32_t* a,
                                         uint32_t b0, uint32_t b1) {
    asm volatile(
        "mma.sync.aligned.m16n8k16.row.col.f32.bf16.bf16.f32 "
        "{%0,%1,%2,%3}, {%4,%5,%6,%7}, {%8,%9}, {%0,%1,%2,%3};"
        : "+f"(d[0]), "+f"(d[1]), "+f"(d[2]), "+f"(d[3])
        : "r"(a[0]), "r"(a[1]), "r"(a[2]), "r"(a[3]), "r"(b0), "r"(b1));
}
__device__ __forceinline__ void cpa16(uint32_t s, const void* g) {
    asm volatile("cp.async.cg.shared.global [%0], [%1], 16;" :: "r"(s), "l"(g));
}
__device__ __forceinline__ void split_bf16(float v, unsigned short& h, unsigned short& l) {
    __nv_bfloat16 hb = __float2bfloat16_rn(v);
    float r = v - __bfloat162float(hb);
    h = __bfloat16_as_ushort(hb);
    l = __bfloat16_as_ushort(__float2bfloat16_rn(r));
}

// ---------------------------------------------------------------- coeff
__global__ void coeff_kernel(const float* __restrict__ phi) {
    int b = blockIdx.x * blockDim.x + threadIdx.x;
    if (b >= BSZ) return;
    const float TWO_OVER_PI = (float)(2.0 / 3.14159265358979323846);
    float w  = TWO_OVER_PI * phi[b];
    int  wi  = ((int)w) & 3;
    float w2 = w * w, w3 = w2 * w;
    float co[4];
    co[0] = -0.5f * w + w2 - 0.5f * w3;
    co[1] = -2.5f * w2 + 1.5f * w3;
    co[2] =  0.5f * w + 2.0f * w2 - 1.5f * w3;
    co[3] = -0.5f * w2 + 0.5f * w3;
    float c[4];
#pragma unroll
    for (int e = 0; e < 4; ++e) c[e] = co[(e - wi + 5) & 3];
    g_coeff[b] = make_float4(c[0], c[1], c[2], c[3]);
}

// ---------------------------------------------------------------- X convert
__global__ void convX_kernel(const float* __restrict__ X) {
    size_t i = ((size_t)blockIdx.x * 256 + threadIdx.x) * 4;
    float4 f = *(const float4*)(X + i);
    float v[4] = {f.x, f.y, f.z, f.w};
    unsigned short h[4], l[4];
#pragma unroll
    for (int p = 0; p < 4; ++p) split_bf16(v[p], h[p], l[p]);
    *(uint2*)(g_Ahi + i) = make_uint2((uint32_t)h[0] | ((uint32_t)h[1] << 16),
                                      (uint32_t)h[2] | ((uint32_t)h[3] << 16));
    *(uint2*)(g_Alo + i) = make_uint2((uint32_t)l[0] | ((uint32_t)l[1] << 16),
                                      (uint32_t)l[2] | ((uint32_t)l[3] << 16));
}

// ---------------------------------------------------------------- W convert
// W [4][256 k][256 n] f32 -> blocked [chunk=e*8+kc][n 256][k 32] bf16 hi/lo
__global__ void convW3_kernel(const float* __restrict__ Wa,
                              const float* __restrict__ Wb,
                              const float* __restrict__ Wc) {
    int i = blockIdx.x * 256 + threadIdx.x;     // 262144 per layer
    int slot = blockIdx.y;
    const float* W = (slot == 0) ? Wa : (slot == 1) ? Wb : Wc;
    int chunk = i >> 13;
    int n = (i >> 5) & 255;
    int k = i & 31;
    int e = chunk >> 3, kc = chunk & 7;
    float w = W[((e << 8) + kc * 32 + k) * NDIM + n];
    unsigned short h, l;
    split_bf16(w, h, l);
    g_Whi[(size_t)slot * 262144 + i] = __ushort_as_bfloat16(h);
    g_Wlo[(size_t)slot * 262144 + i] = __ushort_as_bfloat16(l);
}

// ---------------------------------------------------------------- B chunk load
__device__ __forceinline__ void load_chunkB(uint32_t sb,
                                            const __nv_bfloat16* __restrict__ Whi,
                                            const __nv_bfloat16* __restrict__ Wlo,
                                            int chunk, int stage, int colbase, int tid) {
    const uint32_t dst = sb + SB_OFF + stage * SB_STAGE;
    const __nv_bfloat16* sH = Whi + (size_t)chunk * 8192;
    const __nv_bfloat16* sL = Wlo + (size_t)chunk * 8192;
    // 512 threads, one 16B hi + one 16B lo request each
    int n = tid >> 2, q = tid & 3;
    cpa16(dst + n * BSTR + q * 16,         sH + (size_t)(colbase + n) * 32 + q * 8);
    cpa16(dst + SB_LO + n * BSTR + q * 16, sL + (size_t)(colbase + n) * 32 + q * 8);
}

// ---------------------------------------------------------------- layer
template <bool RELU, bool BF16OUT>
__global__ void __launch_bounds__(512, 1) layer_hmma(
    const __nv_bfloat16* __restrict__ Xhi,
    const __nv_bfloat16* __restrict__ Xlo,
    const __nv_bfloat16* __restrict__ Whi,
    const __nv_bfloat16* __restrict__ Wlo,
    const float* __restrict__ bias,
    __nv_bfloat16* __restrict__ Ohi,
    __nv_bfloat16* __restrict__ Olo,
    float* __restrict__ Out)
{
    extern __shared__ char smem[];
    const uint32_t sb = smem_u32(smem);
    const int tid = threadIdx.x, lane = tid & 31, wid = tid >> 5;
    const int mwarp = wid >> 1, nwarp = wid & 1;   // 8 M-warps x 2 N-warps
    const int mtile = blockIdx.x >> 1, ch = blockIdx.x & 1;
    const int rowbase = mtile << 7, colbase = ch << 7;

    // A tile: 128 rows x 256 bf16 hi/lo via cp.async (group 0)
#pragma unroll
    for (int u = tid; u < 4096; u += 512) {
        int r = u >> 5, s = u & 31;
        cpa16(sb + r * ASTR + s * 16,         Xhi + (size_t)(rowbase + r) * NDIM + s * 8);
        cpa16(sb + SA_LO + r * ASTR + s * 16, Xlo + (size_t)(rowbase + r) * NDIM + s * 8);
    }
    asm volatile("cp.async.commit_group;" ::: "memory");
    load_chunkB(sb, Whi, Wlo, 0, 0, colbase, tid);
    asm volatile("cp.async.commit_group;" ::: "memory");
    load_chunkB(sb, Whi, Wlo, 1, 1, colbase, tid);
    asm volatile("cp.async.commit_group;" ::: "memory");

    // bias -> smem: [e][128] for this col half
    ((float*)(smem + SBIAS))[tid] = bias[(tid >> 7) * NDIM + colbase + (tid & 127)];

    const int gr0 = rowbase + mwarp * 16 + (lane >> 2);
    const float4 cva = g_coeff[gr0];
    const float4 cvb = g_coeff[gr0 + 8];

    const int lrow = (lane & 7) + (((lane >> 3) & 1) << 3);
    const int lkof = (lane >> 4) << 3;
    const uint32_t aBase = sb + (mwarp * 16 + lrow) * ASTR + lkof * 2;
    const uint32_t bRow  = nwarp * (64 * BSTR) + lrow * BSTR + lkof * 2;

    float acc[32], outv[32];
#pragma unroll
    for (int i = 0; i < 32; ++i) { acc[i] = 0.f; outv[i] = 0.f; }

    int t = 0;
#pragma unroll
    for (int e = 0; e < 4; ++e) {
#pragma unroll 2
        for (int kc = 0; kc < 8; ++kc) {
            if (t < 31) asm volatile("cp.async.wait_group 1;" ::: "memory");
            else        asm volatile("cp.async.wait_group 0;" ::: "memory");
            __syncthreads();
            if (t < 30) {
                load_chunkB(sb, Whi, Wlo, t + 2, (t + 2) % 3, colbase, tid);
                asm volatile("cp.async.commit_group;" ::: "memory");
            }
            const uint32_t bS = sb + SB_OFF + (t % 3) * SB_STAGE;
#pragma unroll
            for (int ks = 0; ks < 2; ++ks) {
                uint32_t ah[4], al[4];
                const uint32_t ak = aBase + (kc * 32 + ks * 16) * 2;
                ldsm4(ah, ak);
                ldsm4(al, ak + SA_LO);
#pragma unroll
                for (int gpp = 0; gpp < 2; ++gpp) {
                    // two 16-col groups -> 4 independent acc tiles in flight
                    uint32_t bha[4], bla[4], bhb[4], blb[4];
                    const uint32_t ba = bS + bRow + gpp * (32 * BSTR) + ks * 32;
                    ldsm4(bha, ba);
                    ldsm4(bhb, ba + 16 * BSTR);
                    ldsm4(bla, ba + SB_LO);
                    ldsm4(blb, ba + SB_LO + 16 * BSTR);
                    float* A0 = acc + gpp * 16;
                    float* A1 = A0 + 4;
                    float* A2 = A0 + 8;
                    float* A3 = A0 + 12;
                    mma16816(A0, ah, bha[0], bha[2]);
                    mma16816(A1, ah, bha[1], bha[3]);
                    mma16816(A2, ah, bhb[0], bhb[2]);
                    mma16816(A3, ah, bhb[1], bhb[3]);
                    mma16816(A0, al, bha[0], bha[2]);
                    mma16816(A1, al, bha[1], bha[3]);
                    mma16816(A2, al, bhb[0], bhb[2]);
                    mma16816(A3, al, bhb[1], bhb[3]);
                    mma16816(A0, ah, bla[0], bla[2]);
                    mma16816(A1, ah, bla[1], bla[3]);
                    mma16816(A2, ah, blb[0], blb[2]);
                    mma16816(A3, ah, blb[1], blb[3]);
                }
            }
            ++t;
        }
        const float ce0 = (e == 0) ? cva.x : (e == 1) ? cva.y : (e == 2) ? cva.z : cva.w;
        const float ce1 = (e == 0) ? cvb.x : (e == 1) ? cvb.y : (e == 2) ? cvb.z : cvb.w;
#pragma unroll
        for (int i = 0; i < 32; i += 4) {
            outv[i]     += ce0 * acc[i];     acc[i]     = 0.f;
            outv[i + 1] += ce0 * acc[i + 1]; acc[i + 1] = 0.f;
            outv[i + 2] += ce1 * acc[i + 2]; acc[i + 2] = 0.f;
            outv[i + 3] += ce1 * acc[i + 3]; acc[i + 3] = 0.f;
        }
    }

    // ---- epilogue: + sum_e c_e * b_e[n], ReLU, store (f32 or bf16 hi/lo)
    const float* bsm = (const float*)(smem + SBIAS);
#pragma unroll
    for (int j = 0; j < 8; ++j) {            // 8 n8-tiles, acc base j*4
        const int nc = nwarp * 64 + j * 8 + (lane & 3) * 2;   // col within half
        const int n0 = colbase + nc;
        float b00 = cva.x * bsm[nc] + cva.y * bsm[128 + nc]
                  + cva.z * bsm[256 + nc] + cva.w * bsm[384 + nc];
        float b01 = cva.x * bsm[nc + 1] + cva.y * bsm[128 + nc + 1]
                  + cva.z * bsm[256 + nc + 1] + cva.w * bsm[384 + nc + 1];
        float b10 = cvb.x * bsm[nc] + cvb.y * bsm[128 + nc]
                  + cvb.z * bsm[256 + nc] + cvb.w * bsm[384 + nc];
        float b11 = cvb.x * bsm[nc + 1] + cvb.y * bsm[128 + nc + 1]
                  + cvb.z * bsm[256 + nc + 1] + cvb.w * bsm[384 + nc + 1];
        const float* o = outv + j * 4;
        float v0 = o[0] + b00, v1 = o[1] + b01;
        float v2 = o[2] + b10, v3 = o[3] + b11;
        if (RELU) {
            v0 = fmaxf(v0, 0.f); v1 = fmaxf(v1, 0.f);
            v2 = fmaxf(v2, 0.f); v3 = fmaxf(v3, 0.f);
        }
        if (BF16OUT) {
            unsigned short h0, l0, h1, l1, h2, l2, h3, l3;
            split_bf16(v0, h0, l0); split_bf16(v1, h1, l1);
            split_bf16(v2, h2, l2); split_bf16(v3, h3, l3);
            size_t p0 = (size_t)gr0 * NDIM + n0;
            size_t p1 = (size_t)(gr0 + 8) * NDIM + n0;
            *(uint32_t*)(Ohi + p0) = (uint32_t)h0 | ((uint32_t)h1 << 16);
            *(uint32_t*)(Olo + p0) = (uint32_t)l0 | ((uint32_t)l1 << 16);
            *(uint32_t*)(Ohi + p1) = (uint32_t)h2 | ((uint32_t)h3 << 16);
            *(uint32_t*)(Olo + p1) = (uint32_t)l2 | ((uint32_t)l3 << 16);
        } else {
            *(float2*)(Out + (size_t)gr0 * NDIM + n0)       = make_float2(v0, v1);
            *(float2*)(Out + (size_t)(gr0 + 8) * NDIM + n0) = make_float2(v2, v3);
        }
    }
}

// ---------------------------------------------------------------- launch
extern "C" void kernel_launch(void* const* d_in, const int* in_sizes, int n_in,
                              void* d_out, int out_size) {
    const float* X   = (const float*)d_in[0];
    const float* phi = (const float*)d_in[1];
    const float* W1  = (const float*)d_in[2];
    const float* b1  = (const float*)d_in[3];
    const float* W2  = (const float*)d_in[4];
    const float* b2  = (const float*)d_in[5];
    const float* W3  = (const float*)d_in[6];
    const float* b3  = (const float*)d_in[7];
    float* out = (float*)d_out;

    __nv_bfloat16 *Whi, *Wlo, *Ahi, *Alo, *Bhi, *Blo;
    cudaGetSymbolAddress((void**)&Whi, g_Whi);
    cudaGetSymbolAddress((void**)&Wlo, g_Wlo);
    cudaGetSymbolAddress((void**)&Ahi, g_Ahi);
    cudaGetSymbolAddress((void**)&Alo, g_Alo);
    cudaGetSymbolAddress((void**)&Bhi, g_Bhi);
    cudaGetSymbolAddress((void**)&Blo, g_Blo);

    cudaFuncSetAttribute(layer_hmma<true, true>,
                         cudaFuncAttributeMaxDynamicSharedMemorySize, SM_TOTAL);
    cudaFuncSetAttribute(layer_hmma<false, false>,
                         cudaFuncAttributeMaxDynamicSharedMemorySize, SM_TOTAL);

    coeff_kernel<<<BSZ / 256, 256>>>(phi);                 // launch 0
    convX_kernel<<<BSZ * NDIM / 1024, 256>>>(X);           // launch 1
    convW3_kernel<<<dim3(1024, 3), 256>>>(W1, W2, W3);     // launch 2

    // L1: A -> B   (launch 3)
    layer_hmma<true, true><<<1024, 512, SM_TOTAL>>>(
        Ahi, Alo, Whi, Wlo, b1, Bhi, Blo, nullptr);
    // L2: B -> A   (launch 4)
    layer_hmma<true, true><<<1024, 512, SM_TOTAL>>>(
        Bhi, Blo, Whi + 262144, Wlo + 262144, b2, Ahi, Alo, nullptr);
    // L3: A -> out (launch 5 — ncu -s 5 lands here)
    layer_hmma<false, false><<<1024, 512, SM_TOTAL>>>(
        Ahi, Alo, Whi + 524288, Wlo + 524288, b3, nullptr, nullptr, out);
}

// round 8
// speedup vs baseline: 3.6163x; 1.0811x over previous
#include <cuda_runtime.h>
#include <cuda_bf16.h>
#include <cstdint>

// MotionPrediction: B=65536, 3 cyclic-MoE layers, dims 256, 4 experts.
// out = sum_e c_e (.) (X @ W_e + b_e), ReLU on layers 1,2.
// HMMA mma.sync m16n8k16 bf16, hi/lo split (3 products) ~ fp32 accuracy.
// R7: 4 B-stages, fully unrolled kc loop (static smem addresses), prefetch
// distance 3 with wait_group 2. 512 threads/CTA.

#define BSZ  65536
#define NDIM 256

__device__ __align__(16) __nv_bfloat16 g_Whi[3 * 4 * NDIM * NDIM]; // [slot][chunk][n256][k32]
__device__ __align__(16) __nv_bfloat16 g_Wlo[3 * 4 * NDIM * NDIM];
__device__ __align__(16) __nv_bfloat16 g_Ahi[BSZ * NDIM];
__device__ __align__(16) __nv_bfloat16 g_Alo[BSZ * NDIM];
__device__ __align__(16) __nv_bfloat16 g_Bhi[BSZ * NDIM];
__device__ __align__(16) __nv_bfloat16 g_Blo[BSZ * NDIM];
__device__ float4 g_coeff[BSZ];

// ---- SMEM map (bytes) ----
#define ASTR     528                    // A row stride (256 bf16 + pad)
#define SA_LO    67584                  // A_lo = A_hi + 128*528
#define SB_OFF   135168                 // 4 B stages
#define SB_STAGE 20480                  // per stage: hi 10240 + lo 10240
#define SB_LO    10240
#define BSTR     80                     // B row stride (32 bf16 + pad)
#define SBIAS    217088                 // 512 floats
#define SM_TOTAL 219136

// ---------------------------------------------------------------- helpers
__device__ __forceinline__ uint32_t smem_u32(const void* p) {
    uint32_t a;
    asm("{ .reg .u64 t; cvta.to.shared.u64 t, %1; cvt.u32.u64 %0, t; }"
        : "=r"(a) : "l"(p));
    return a;
}
__device__ __forceinline__ void ldsm4(uint32_t* r, uint32_t a) {
    asm volatile("ldmatrix.sync.aligned.m8n8.x4.shared.b16 {%0,%1,%2,%3}, [%4];"
                 : "=r"(r[0]), "=r"(r[1]), "=r"(r[2]), "=r"(r[3]) : "r"(a));
}
__device__ __forceinline__ void mma16816(float* d, const uint32_t* a,
                                         uint32_t b0, uint32_t b1) {
    asm volatile(
        "mma.sync.aligned.m16n8k16.row.col.f32.bf16.bf16.f32 "
        "{%0,%1,%2,%3}, {%4,%5,%6,%7}, {%8,%9}, {%0,%1,%2,%3};"
        : "+f"(d[0]), "+f"(d[1]), "+f"(d[2]), "+f"(d[3])
        : "r"(a[0]), "r"(a[1]), "r"(a[2]), "r"(a[3]), "r"(b0), "r"(b1));
}
__device__ __forceinline__ void cpa16(uint32_t s, const void* g) {
    asm volatile("cp.async.cg.shared.global [%0], [%1], 16;" :: "r"(s), "l"(g));
}
__device__ __forceinline__ void split_bf16(float v, unsigned short& h, unsigned short& l) {
    __nv_bfloat16 hb = __float2bfloat16_rn(v);
    float r = v - __bfloat162float(hb);
    h = __bfloat16_as_ushort(hb);
    l = __bfloat16_as_ushort(__float2bfloat16_rn(r));
}

// ---------------------------------------------------------------- coeff
__global__ void coeff_kernel(const float* __restrict__ phi) {
    int b = blockIdx.x * blockDim.x + threadIdx.x;
    if (b >= BSZ) return;
    const float TWO_OVER_PI = (float)(2.0 / 3.14159265358979323846);
    float w  = TWO_OVER_PI * phi[b];
    int  wi  = ((int)w) & 3;
    float w2 = w * w, w3 = w2 * w;
    float co[4];
    co[0] = -0.5f * w + w2 - 0.5f * w3;
    co[1] = -2.5f * w2 + 1.5f * w3;
    co[2] =  0.5f * w + 2.0f * w2 - 1.5f * w3;
    co[3] = -0.5f * w2 + 0.5f * w3;
    float c[4];
#pragma unroll
    for (int e = 0; e < 4; ++e) c[e] = co[(e - wi + 5) & 3];
    g_coeff[b] = make_float4(c[0], c[1], c[2], c[3]);
}

// ---------------------------------------------------------------- X convert
__global__ void convX_kernel(const float* __restrict__ X) {
    size_t i = ((size_t)blockIdx.x * 256 + threadIdx.x) * 4;
    float4 f = *(const float4*)(X + i);
    float v[4] = {f.x, f.y, f.z, f.w};
    unsigned short h[4], l[4];
#pragma unroll
    for (int p = 0; p < 4; ++p) split_bf16(v[p], h[p], l[p]);
    *(uint2*)(g_Ahi + i) = make_uint2((uint32_t)h[0] | ((uint32_t)h[1] << 16),
                                      (uint32_t)h[2] | ((uint32_t)h[3] << 16));
    *(uint2*)(g_Alo + i) = make_uint2((uint32_t)l[0] | ((uint32_t)l[1] << 16),
                                      (uint32_t)l[2] | ((uint32_t)l[3] << 16));
}

// ---------------------------------------------------------------- W convert
// W [4][256 k][256 n] f32 -> blocked [chunk=e*8+kc][n 256][k 32] bf16 hi/lo
__global__ void convW3_kernel(const float* __restrict__ Wa,
                              const float* __restrict__ Wb,
                              const float* __restrict__ Wc) {
    int i = blockIdx.x * 256 + threadIdx.x;     // 262144 per layer
    int slot = blockIdx.y;
    const float* W = (slot == 0) ? Wa : (slot == 1) ? Wb : Wc;
    int chunk = i >> 13;
    int n = (i >> 5) & 255;
    int k = i & 31;
    int e = chunk >> 3, kc = chunk & 7;
    float w = W[((e << 8) + kc * 32 + k) * NDIM + n];
    unsigned short h, l;
    split_bf16(w, h, l);
    g_Whi[(size_t)slot * 262144 + i] = __ushort_as_bfloat16(h);
    g_Wlo[(size_t)slot * 262144 + i] = __ushort_as_bfloat16(l);
}

// ---------------------------------------------------------------- B chunk load
__device__ __forceinline__ void load_chunkB(uint32_t dst,
                                            const __nv_bfloat16* __restrict__ sH,
                                            const __nv_bfloat16* __restrict__ sL,
                                            uint32_t soff) {
    cpa16(dst,         (const char*)sH + soff);
    cpa16(dst + SB_LO, (const char*)sL + soff);
}

// ---------------------------------------------------------------- layer
template <bool RELU, bool BF16OUT>
__global__ void __launch_bounds__(512, 1) layer_hmma(
    const __nv_bfloat16* __restrict__ Xhi,
    const __nv_bfloat16* __restrict__ Xlo,
    const __nv_bfloat16* __restrict__ Whi,
    const __nv_bfloat16* __restrict__ Wlo,
    const float* __restrict__ bias,
    __nv_bfloat16* __restrict__ Ohi,
    __nv_bfloat16* __restrict__ Olo,
    float* __restrict__ Out)
{
    extern __shared__ char smem[];
    const uint32_t sb = smem_u32(smem);
    const int tid = threadIdx.x, lane = tid & 31, wid = tid >> 5;
    const int mwarp = wid >> 1, nwarp = wid & 1;   // 8 M-warps x 2 N-warps
    const int mtile = blockIdx.x >> 1, ch = blockIdx.x & 1;
    const int rowbase = mtile << 7, colbase = ch << 7;

    // per-thread source offset within a W chunk (bytes): row (colbase+n), 16B quad q
    const int bn = tid >> 2, bq = tid & 3;
    const uint32_t wsrc_off = (uint32_t)(colbase + bn) * 64 + bq * 16;  // bytes into 8192*2B chunk
    const uint32_t bdst = sb + SB_OFF + bn * BSTR + bq * 16;            // + stage*SB_STAGE

    // A tile: 128 rows x 256 bf16 hi/lo via cp.async (group 0)
#pragma unroll
    for (int u = tid; u < 4096; u += 512) {
        int r = u >> 5, s = u & 31;
        cpa16(sb + r * ASTR + s * 16,         Xhi + (size_t)(rowbase + r) * NDIM + s * 8);
        cpa16(sb + SA_LO + r * ASTR + s * 16, Xlo + (size_t)(rowbase + r) * NDIM + s * 8);
    }
    asm volatile("cp.async.commit_group;" ::: "memory");
    // preload chunks 0,1,2 into stages 0,1,2
#pragma unroll
    for (int c = 0; c < 3; ++c) {
        load_chunkB(bdst + c * SB_STAGE,
                    Whi + (size_t)c * 8192, Wlo + (size_t)c * 8192, wsrc_off);
        asm volatile("cp.async.commit_group;" ::: "memory");
    }

    // bias -> smem: [e][128] for this col half
    ((float*)(smem + SBIAS))[tid] = bias[(tid >> 7) * NDIM + colbase + (tid & 127)];

    const int gr0 = rowbase + mwarp * 16 + (lane >> 2);
    const float4 cva = g_coeff[gr0];
    const float4 cvb = g_coeff[gr0 + 8];

    const int lrow = (lane & 7) + (((lane >> 3) & 1) << 3);
    const int lkof = (lane >> 4) << 3;
    const uint32_t aBase = sb + (mwarp * 16 + lrow) * ASTR + lkof * 2;
    const uint32_t bRow  = sb + SB_OFF + nwarp * (64 * BSTR) + lrow * BSTR + lkof * 2;

    float acc[32], outv[32];
#pragma unroll
    for (int i = 0; i < 32; ++i) { acc[i] = 0.f; outv[i] = 0.f; }

#pragma unroll
    for (int e = 0; e < 4; ++e) {
#pragma unroll
        for (int kc = 0; kc < 8; ++kc) {
            const int t = e * 8 + kc;        // compile-time within unrolled body
            asm volatile("cp.async.wait_group 2;" ::: "memory");
            __syncthreads();
            if (t < 29) {                    // prefetch chunk t+3 into stage (t+3)&3
                load_chunkB(bdst + ((t + 3) & 3) * SB_STAGE,
                            Whi + (size_t)(t + 3) * 8192,
                            Wlo + (size_t)(t + 3) * 8192, wsrc_off);
                asm volatile("cp.async.commit_group;" ::: "memory");
            }
            const uint32_t bS = bRow + (kc & 3) * SB_STAGE;  // static offset
#pragma unroll
            for (int ks = 0; ks < 2; ++ks) {
                uint32_t ah[4], al[4];
                const uint32_t ak = aBase + (kc * 32 + ks * 16) * 2;
                ldsm4(ah, ak);
                ldsm4(al, ak + SA_LO);
#pragma unroll
                for (int gpp = 0; gpp < 2; ++gpp) {
                    // two 16-col groups -> 4 independent acc tiles in flight
                    uint32_t bha[4], bla[4], bhb[4], blb[4];
                    const uint32_t ba = bS + gpp * (32 * BSTR) + ks * 32;
                    ldsm4(bha, ba);
                    ldsm4(bhb, ba + 16 * BSTR);
                    ldsm4(bla, ba + SB_LO);
                    ldsm4(blb, ba + SB_LO + 16 * BSTR);
                    float* A0 = acc + gpp * 16;
                    float* A1 = A0 + 4;
                    float* A2 = A0 + 8;
                    float* A3 = A0 + 12;
                    mma16816(A0, ah, bha[0], bha[2]);
                    mma16816(A1, ah, bha[1], bha[3]);
                    mma16816(A2, ah, bhb[0], bhb[2]);
                    mma16816(A3, ah, bhb[1], bhb[3]);
                    mma16816(A0, al, bha[0], bha[2]);
                    mma16816(A1, al, bha[1], bha[3]);
                    mma16816(A2, al, bhb[0], bhb[2]);
                    mma16816(A3, al, bhb[1], bhb[3]);
                    mma16816(A0, ah, bla[0], bla[2]);
                    mma16816(A1, ah, bla[1], bla[3]);
                    mma16816(A2, ah, blb[0], blb[2]);
                    mma16816(A3, ah, blb[1], blb[3]);
                }
            }
        }
        const float ce0 = (e == 0) ? cva.x : (e == 1) ? cva.y : (e == 2) ? cva.z : cva.w;
        const float ce1 = (e == 0) ? cvb.x : (e == 1) ? cvb.y : (e == 2) ? cvb.z : cvb.w;
#pragma unroll
        for (int i = 0; i < 32; i += 4) {
            outv[i]     += ce0 * acc[i];     acc[i]     = 0.f;
            outv[i + 1] += ce0 * acc[i + 1]; acc[i + 1] = 0.f;
            outv[i + 2] += ce1 * acc[i + 2]; acc[i + 2] = 0.f;
            outv[i + 3] += ce1 * acc[i + 3]; acc[i + 3] = 0.f;
        }
    }

    // ---- epilogue: + sum_e c_e * b_e[n], ReLU, store (f32 or bf16 hi/lo)
    const float* bsm = (const float*)(smem + SBIAS);
#pragma unroll
    for (int j = 0; j < 8; ++j) {            // 8 n8-tiles, acc base j*4
        const int nc = nwarp * 64 + j * 8 + (lane & 3) * 2;   // col within half
        const int n0 = colbase + nc;
        float b00 = cva.x * bsm[nc] + cva.y * bsm[128 + nc]
                  + cva.z * bsm[256 + nc] + cva.w * bsm[384 + nc];
        float b01 = cva.x * bsm[nc + 1] + cva.y * bsm[128 + nc + 1]
                  + cva.z * bsm[256 + nc + 1] + cva.w * bsm[384 + nc + 1];
        float b10 = cvb.x * bsm[nc] + cvb.y * bsm[128 + nc]
                  + cvb.z * bsm[256 + nc] + cvb.w * bsm[384 + nc];
        float b11 = cvb.x * bsm[nc + 1] + cvb.y * bsm[128 + nc + 1]
                  + cvb.z * bsm[256 + nc + 1] + cvb.w * bsm[384 + nc + 1];
        const float* o = outv + j * 4;
        float v0 = o[0] + b00, v1 = o[1] + b01;
        float v2 = o[2] + b10, v3 = o[3] + b11;
        if (RELU) {
            v0 = fmaxf(v0, 0.f); v1 = fmaxf(v1, 0.f);
            v2 = fmaxf(v2, 0.f); v3 = fmaxf(v3, 0.f);
        }
        if (BF16OUT) {
            unsigned short h0, l0, h1, l1, h2, l2, h3, l3;
            split_bf16(v0, h0, l0); split_bf16(v1, h1, l1);
            split_bf16(v2, h2, l2); split_bf16(v3, h3, l3);
            size_t p0 = (size_t)gr0 * NDIM + n0;
            size_t p1 = (size_t)(gr0 + 8) * NDIM + n0;
            *(uint32_t*)(Ohi + p0) = (uint32_t)h0 | ((uint32_t)h1 << 16);
            *(uint32_t*)(Olo + p0) = (uint32_t)l0 | ((uint32_t)l1 << 16);
            *(uint32_t*)(Ohi + p1) = (uint32_t)h2 | ((uint32_t)h3 << 16);
            *(uint32_t*)(Olo + p1) = (uint32_t)l2 | ((uint32_t)l3 << 16);
        } else {
            *(float2*)(Out + (size_t)gr0 * NDIM + n0)       = make_float2(v0, v1);
            *(float2*)(Out + (size_t)(gr0 + 8) * NDIM + n0) = make_float2(v2, v3);
        }
    }
}

// ---------------------------------------------------------------- launch
extern "C" void kernel_launch(void* const* d_in, const int* in_sizes, int n_in,
                              void* d_out, int out_size) {
    const float* X   = (const float*)d_in[0];
    const float* phi = (const float*)d_in[1];
    const float* W1  = (const float*)d_in[2];
    const float* b1  = (const float*)d_in[3];
    const float* W2  = (const float*)d_in[4];
    const float* b2  = (const float*)d_in[5];
    const float* W3  = (const float*)d_in[6];
    const float* b3  = (const float*)d_in[7];
    float* out = (float*)d_out;

    __nv_bfloat16 *Whi, *Wlo, *Ahi, *Alo, *Bhi, *Blo;
    cudaGetSymbolAddress((void**)&Whi, g_Whi);
    cudaGetSymbolAddress((void**)&Wlo, g_Wlo);
    cudaGetSymbolAddress((void**)&Ahi, g_Ahi);
    cudaGetSymbolAddress((void**)&Alo, g_Alo);
    cudaGetSymbolAddress((void**)&Bhi, g_Bhi);
    cudaGetSymbolAddress((void**)&Blo, g_Blo);

    cudaFuncSetAttribute(layer_hmma<true, true>,
                         cudaFuncAttributeMaxDynamicSharedMemorySize, SM_TOTAL);
    cudaFuncSetAttribute(layer_hmma<false, false>,
                         cudaFuncAttributeMaxDynamicSharedMemorySize, SM_TOTAL);

    coeff_kernel<<<BSZ / 256, 256>>>(phi);                 // launch 0
    convX_kernel<<<BSZ * NDIM / 1024, 256>>>(X);           // launch 1
    convW3_kernel<<<dim3(1024, 3), 256>>>(W1, W2, W3);     // launch 2

    // L1: A -> B   (launch 3)
    layer_hmma<true, true><<<1024, 512, SM_TOTAL>>>(
        Ahi, Alo, Whi, Wlo, b1, Bhi, Blo, nullptr);
    // L2: B -> A   (launch 4)
    layer_hmma<true, true><<<1024, 512, SM_TOTAL>>>(
        Bhi, Blo, Whi + 262144, Wlo + 262144, b2, Ahi, Alo, nullptr);
    // L3: A -> out (launch 5 — ncu -s 5 lands here)
    layer_hmma<false, false><<<1024, 512, SM_TOTAL>>>(
        Ahi, Alo, Whi + 524288, Wlo + 524288, b3, nullptr, nullptr, out);
}